// round 1
// baseline (speedup 1.0000x reference)
#include <cuda_runtime.h>
#include <math.h>

#define B_ 256
#define N_ 4096
#define D_ 128
#define C_ 32
#define BSPLIT 2   // each n handled by 2 warps, each covering B/2 batches

// Scratch (allocation-free rule: __device__ globals)
__device__ float g_fwp[N_ * D_];   // softplus(feature_weights)
__device__ float g_wf [N_ * D_];   // softplus(fw) * (-|distance_weights|)
__device__ float g_rowsum[B_];     // sum_n activations[b][n]

// ---------------------------------------------------------------------------
// Kernel 1: precompute per-(n,d) weights; zero rowsum (must re-zero per replay)
// ---------------------------------------------------------------------------
__global__ void __launch_bounds__(256) prep_kernel(const float* __restrict__ fw,
                                                   const float* __restrict__ dw)
{
    int i = blockIdx.x * blockDim.x + threadIdx.x;
    if (i < N_ * D_) {
        float x  = fw[i];
        float sp = (x > 20.0f) ? x : log1pf(expf(x));
        g_fwp[i] = sp;
        g_wf[i]  = sp * (-fabsf(dw[i]));
    }
    if (blockIdx.x == 0 && threadIdx.x < B_) g_rowsum[threadIdx.x] = 0.0f;
}

// ---------------------------------------------------------------------------
// Kernel 2: main. One warp owns one (n, b-half). Case rows live in registers;
// loop over b streaming delta writes (512B/warp/iter) and producing
// activations + rowsum atomics.
// ---------------------------------------------------------------------------
__global__ void __launch_bounds__(256) main_kernel(const float* __restrict__ q,
                                                   const float* __restrict__ cases,
                                                   const float* __restrict__ bias,
                                                   float* __restrict__ delta,
                                                   float* __restrict__ act)
{
    int gw   = (blockIdx.x * blockDim.x + threadIdx.x) >> 5;  // global warp id
    int lane = threadIdx.x & 31;
    int n    = gw & (N_ - 1);        // consecutive warps -> consecutive n (write locality)
    int bh   = gw >> 12;             // 0 or 1 (N_=4096 -> 12 bits)
    if (bh >= BSPLIT) return;

    // Case-local rows, register resident: 3 x float4 per lane (covers d = 4*lane..4*lane+3)
    const float4* c4p = reinterpret_cast<const float4*>(cases + (size_t)n * D_);
    const float4* f4p = reinterpret_cast<const float4*>(g_fwp + (size_t)n * D_);
    const float4* w4p = reinterpret_cast<const float4*>(g_wf  + (size_t)n * D_);
    float4 c4 = __ldg(c4p + lane);
    float4 f4 = __ldg(f4p + lane);
    float4 w4 = __ldg(w4p + lane);
    float  bn = __ldg(bias + n);

    const int b0 = bh * (B_ / BSPLIT);
    const int b1 = b0 + (B_ / BSPLIT);

    const float4* q4base = reinterpret_cast<const float4*>(q);
    float4*       d4base = reinterpret_cast<float4*>(delta);

    for (int b = b0; b < b1; b++) {
        float4 q4 = __ldg(q4base + (size_t)b * (D_ / 4) + lane);  // L1-hit (shared across warps)

        float dx = q4.x - c4.x;
        float dy = q4.y - c4.y;
        float dz = q4.z - c4.z;
        float dwv = q4.w - c4.w;
        dx *= dx; dy *= dy; dz *= dz; dwv *= dwv;

        float4 o;
        o.x = dx * f4.x; o.y = dy * f4.y; o.z = dz * f4.z; o.w = dwv * f4.w;

        // per-lane partial of sum_d delta*w  (note: delta*w = d2*fwp*wneg = d2*wf)
        float a = dx * w4.x;
        a = fmaf(dy, w4.y, a);
        a = fmaf(dz, w4.z, a);
        a = fmaf(dwv, w4.w, a);

        d4base[((size_t)b * N_ + n) * (D_ / 4) + lane] = o;

        // warp reduce
        a += __shfl_xor_sync(0xffffffffu, a, 16);
        a += __shfl_xor_sync(0xffffffffu, a, 8);
        a += __shfl_xor_sync(0xffffffffu, a, 4);
        a += __shfl_xor_sync(0xffffffffu, a, 2);
        a += __shfl_xor_sync(0xffffffffu, a, 1);

        if (lane == 0) {
            float s  = a + bn;
            float av = 1.0f / (1.0f + expf(-s));
            act[(size_t)b * N_ + n] = av;
            atomicAdd(&g_rowsum[b], av);   // no return use -> REDG
        }
    }
}

// ---------------------------------------------------------------------------
// Kernel 3: y_hat = (act / (rowsum + 0.01)) @ targets.
// 32 blocks x 8 b each; 8 warps/block, warp w owns 4 c-columns.
// ---------------------------------------------------------------------------
__global__ void __launch_bounds__(256) yhat_kernel(const float* __restrict__ act,
                                                   const float* __restrict__ targets,
                                                   float* __restrict__ yhat)
{
    int b0   = blockIdx.x * 8;
    int w    = threadIdx.x >> 5;
    int lane = threadIdx.x & 31;
    int c0   = w * 4;

    float acc[8][4];
    #pragma unroll
    for (int i = 0; i < 8; i++)
        #pragma unroll
        for (int j = 0; j < 4; j++) acc[i][j] = 0.0f;

    for (int n = lane; n < N_; n += 32) {
        float4 t = __ldg(reinterpret_cast<const float4*>(targets + (size_t)n * C_ + c0));
        #pragma unroll
        for (int i = 0; i < 8; i++) {
            float a = __ldg(act + (size_t)(b0 + i) * N_ + n);
            acc[i][0] = fmaf(a, t.x, acc[i][0]);
            acc[i][1] = fmaf(a, t.y, acc[i][1]);
            acc[i][2] = fmaf(a, t.z, acc[i][2]);
            acc[i][3] = fmaf(a, t.w, acc[i][3]);
        }
    }

    #pragma unroll
    for (int i = 0; i < 8; i++)
        #pragma unroll
        for (int j = 0; j < 4; j++) {
            float v = acc[i][j];
            v += __shfl_xor_sync(0xffffffffu, v, 16);
            v += __shfl_xor_sync(0xffffffffu, v, 8);
            v += __shfl_xor_sync(0xffffffffu, v, 4);
            v += __shfl_xor_sync(0xffffffffu, v, 2);
            v += __shfl_xor_sync(0xffffffffu, v, 1);
            acc[i][j] = v;
        }

    if (lane == 0) {
        #pragma unroll
        for (int i = 0; i < 8; i++) {
            float inv = 1.0f / (g_rowsum[b0 + i] + 0.01f);
            #pragma unroll
            for (int j = 0; j < 4; j++)
                yhat[(size_t)(b0 + i) * C_ + c0 + j] = acc[i][j] * inv;
        }
    }
}

// ---------------------------------------------------------------------------
// Launch. Inputs (metadata order): queries, cases, targets, feature_weights,
// distance_weights, ca_bias. Output: y_hat | activations | delta (tuple order,
// row-major flattened).
// ---------------------------------------------------------------------------
extern "C" void kernel_launch(void* const* d_in, const int* in_sizes, int n_in,
                              void* d_out, int out_size)
{
    const float* queries = (const float*)d_in[0];
    const float* cases   = (const float*)d_in[1];
    const float* targets = (const float*)d_in[2];
    const float* fw      = (const float*)d_in[3];
    const float* dw      = (const float*)d_in[4];
    const float* bias    = (const float*)d_in[5];

    float* out   = (float*)d_out;
    float* yhat  = out;                                   // B*C    = 8192
    float* act   = out + (size_t)B_ * C_;                 // B*N    = 1048576
    float* delta = out + (size_t)B_ * C_ + (size_t)B_ * N_;

    // 1) precompute fwp / wf, zero rowsum
    prep_kernel<<<(N_ * D_ + 255) / 256, 256>>>(fw, dw);

    // 2) main: N_*BSPLIT warps, 8 warps/block
    int total_warps = N_ * BSPLIT;
    main_kernel<<<total_warps / 8, 256>>>(queries, cases, bias, delta, act);

    // 3) y_hat
    yhat_kernel<<<B_ / 8, 256>>>(act, targets, yhat);
}

// round 2
// speedup vs baseline: 5.8204x; 5.8204x over previous
#include <cuda_runtime.h>
#include <math.h>

#define B_ 256
#define N_ 4096
#define D_ 128
#define C_ 32
#define BSPLIT 2   // each n handled by 2 warps, each covering B/2 batches

// ---------------------------------------------------------------------------
// Main kernel: one warp owns (n, b-half). Case row + weights computed once
// into registers; loop over b streaming 512B delta writes per iteration.
// NO atomics — row sums are recomputed in the epilogue kernel from act.
// ---------------------------------------------------------------------------
__global__ void __launch_bounds__(256) main_kernel(const float* __restrict__ q,
                                                   const float* __restrict__ cases,
                                                   const float* __restrict__ fw,
                                                   const float* __restrict__ dwt,
                                                   const float* __restrict__ bias,
                                                   float* __restrict__ delta,
                                                   float* __restrict__ act)
{
    int gw   = (blockIdx.x * blockDim.x + threadIdx.x) >> 5;  // global warp id
    int lane = threadIdx.x & 31;
    int n    = gw & (N_ - 1);        // consecutive warps -> consecutive n
    int bh   = gw >> 12;             // 0 or 1
    if (bh >= BSPLIT) return;

    // Register-resident per-n data: cases row, softplus(fw), wf = sp * -|dw|
    const float4* c4p = reinterpret_cast<const float4*>(cases + (size_t)n * D_);
    const float4* f4p = reinterpret_cast<const float4*>(fw    + (size_t)n * D_);
    const float4* w4p = reinterpret_cast<const float4*>(dwt   + (size_t)n * D_);
    float4 c4 = __ldg(c4p + lane);
    float4 fr = __ldg(f4p + lane);
    float4 dr = __ldg(w4p + lane);
    float  bn = __ldg(bias + n);

    // softplus per element (stable)
    float4 f4;
    f4.x = (fr.x > 20.0f) ? fr.x : log1pf(expf(fr.x));
    f4.y = (fr.y > 20.0f) ? fr.y : log1pf(expf(fr.y));
    f4.z = (fr.z > 20.0f) ? fr.z : log1pf(expf(fr.z));
    f4.w = (fr.w > 20.0f) ? fr.w : log1pf(expf(fr.w));

    float4 w4;
    w4.x = f4.x * (-fabsf(dr.x));
    w4.y = f4.y * (-fabsf(dr.y));
    w4.z = f4.z * (-fabsf(dr.z));
    w4.w = f4.w * (-fabsf(dr.w));

    const int b0 = bh * (B_ / BSPLIT);
    const int b1 = b0 + (B_ / BSPLIT);

    const float4* q4base = reinterpret_cast<const float4*>(q);
    float4*       d4base = reinterpret_cast<float4*>(delta);

    for (int b = b0; b < b1; b++) {
        float4 q4 = __ldg(q4base + (size_t)b * (D_ / 4) + lane);

        float dx = q4.x - c4.x;
        float dy = q4.y - c4.y;
        float dz = q4.z - c4.z;
        float dwv = q4.w - c4.w;
        dx *= dx; dy *= dy; dz *= dz; dwv *= dwv;

        float4 o;
        o.x = dx * f4.x; o.y = dy * f4.y; o.z = dz * f4.z; o.w = dwv * f4.w;

        // per-lane partial of sum_d delta*w   (delta*w = d2 * wf)
        float a = dx * w4.x;
        a = fmaf(dy,  w4.y, a);
        a = fmaf(dz,  w4.z, a);
        a = fmaf(dwv, w4.w, a);

        // streaming store — evict-first, don't pollute L2
        __stcs(&d4base[((size_t)b * N_ + n) * (D_ / 4) + lane], o);

        // warp reduce
        a += __shfl_xor_sync(0xffffffffu, a, 16);
        a += __shfl_xor_sync(0xffffffffu, a, 8);
        a += __shfl_xor_sync(0xffffffffu, a, 4);
        a += __shfl_xor_sync(0xffffffffu, a, 2);
        a += __shfl_xor_sync(0xffffffffu, a, 1);

        if (lane == 0) {
            float s  = a + bn;
            float av = 1.0f / (1.0f + expf(-s));
            act[(size_t)b * N_ + n] = av;
        }
    }
}

// ---------------------------------------------------------------------------
// Epilogue: y_hat = (act / (rowsum + 0.01)) @ targets, rowsum computed inline.
// 32 blocks x 8 b each; 8 warps/block, warp w owns 4 c-columns.
// ---------------------------------------------------------------------------
__global__ void __launch_bounds__(256) yhat_kernel(const float* __restrict__ act,
                                                   const float* __restrict__ targets,
                                                   float* __restrict__ yhat)
{
    int b0   = blockIdx.x * 8;
    int w    = threadIdx.x >> 5;
    int lane = threadIdx.x & 31;
    int c0   = w * 4;

    float acc[8][4];
    float srow[8];
    #pragma unroll
    for (int i = 0; i < 8; i++) {
        srow[i] = 0.0f;
        #pragma unroll
        for (int j = 0; j < 4; j++) acc[i][j] = 0.0f;
    }

    for (int n = lane; n < N_; n += 32) {
        float4 t = __ldg(reinterpret_cast<const float4*>(targets + (size_t)n * C_ + c0));
        #pragma unroll
        for (int i = 0; i < 8; i++) {
            float a = __ldg(act + (size_t)(b0 + i) * N_ + n);
            srow[i] += a;
            acc[i][0] = fmaf(a, t.x, acc[i][0]);
            acc[i][1] = fmaf(a, t.y, acc[i][1]);
            acc[i][2] = fmaf(a, t.z, acc[i][2]);
            acc[i][3] = fmaf(a, t.w, acc[i][3]);
        }
    }

    #pragma unroll
    for (int i = 0; i < 8; i++) {
        #pragma unroll
        for (int j = 0; j < 4; j++) {
            float v = acc[i][j];
            v += __shfl_xor_sync(0xffffffffu, v, 16);
            v += __shfl_xor_sync(0xffffffffu, v, 8);
            v += __shfl_xor_sync(0xffffffffu, v, 4);
            v += __shfl_xor_sync(0xffffffffu, v, 2);
            v += __shfl_xor_sync(0xffffffffu, v, 1);
            acc[i][j] = v;
        }
        float s = srow[i];
        s += __shfl_xor_sync(0xffffffffu, s, 16);
        s += __shfl_xor_sync(0xffffffffu, s, 8);
        s += __shfl_xor_sync(0xffffffffu, s, 4);
        s += __shfl_xor_sync(0xffffffffu, s, 2);
        s += __shfl_xor_sync(0xffffffffu, s, 1);
        srow[i] = s;
    }

    if (lane == 0) {
        #pragma unroll
        for (int i = 0; i < 8; i++) {
            float inv = 1.0f / (srow[i] + 0.01f);
            #pragma unroll
            for (int j = 0; j < 4; j++)
                yhat[(size_t)(b0 + i) * C_ + c0 + j] = acc[i][j] * inv;
        }
    }
}

// ---------------------------------------------------------------------------
// Launch. Inputs: queries, cases, targets, feature_weights, distance_weights,
// ca_bias. Output layout: y_hat | activations | delta.
// ---------------------------------------------------------------------------
extern "C" void kernel_launch(void* const* d_in, const int* in_sizes, int n_in,
                              void* d_out, int out_size)
{
    const float* queries = (const float*)d_in[0];
    const float* cases   = (const float*)d_in[1];
    const float* targets = (const float*)d_in[2];
    const float* fw      = (const float*)d_in[3];
    const float* dw      = (const float*)d_in[4];
    const float* bias    = (const float*)d_in[5];

    float* out   = (float*)d_out;
    float* yhat  = out;                                   // B*C
    float* act   = out + (size_t)B_ * C_;                 // B*N
    float* delta = out + (size_t)B_ * C_ + (size_t)B_ * N_;

    int total_warps = N_ * BSPLIT;
    main_kernel<<<total_warps / 8, 256>>>(queries, cases, fw, dw, bias, delta, act);
    yhat_kernel<<<B_ / 8, 256>>>(act, targets, yhat);
}

// round 3
// speedup vs baseline: 8.1915x; 1.4074x over previous
#include <cuda_runtime.h>
#include <math.h>

#define B_ 256
#define N_ 4096
#define D_ 128
#define C_ 32
#define BSPLIT 2     // each n handled by 2 warps, each covering B/2 batches
#define NCHUNK 16    // n-dimension split for the yhat partial kernel

// Scratch (allocation-free rule: __device__ globals)
__device__ float g_partial[NCHUNK][B_][C_];  // partial y_hat accumulations
__device__ float g_psum[NCHUNK][B_];         // partial row sums of activations

// ---------------------------------------------------------------------------
// Main kernel: one warp owns (n, b-half). Case row + weights computed once
// into registers; loop over b streaming 512B delta writes per iteration.
// ---------------------------------------------------------------------------
__global__ void __launch_bounds__(256) main_kernel(const float* __restrict__ q,
                                                   const float* __restrict__ cases,
                                                   const float* __restrict__ fw,
                                                   const float* __restrict__ dwt,
                                                   const float* __restrict__ bias,
                                                   float* __restrict__ delta,
                                                   float* __restrict__ act)
{
    int gw   = (blockIdx.x * blockDim.x + threadIdx.x) >> 5;  // global warp id
    int lane = threadIdx.x & 31;
    int n    = gw & (N_ - 1);        // consecutive warps -> consecutive n
    int bh   = gw >> 12;             // 0 or 1
    if (bh >= BSPLIT) return;

    // Register-resident per-n data: cases row, softplus(fw), wf = sp * -|dw|
    const float4* c4p = reinterpret_cast<const float4*>(cases + (size_t)n * D_);
    const float4* f4p = reinterpret_cast<const float4*>(fw    + (size_t)n * D_);
    const float4* w4p = reinterpret_cast<const float4*>(dwt   + (size_t)n * D_);
    float4 c4 = __ldg(c4p + lane);
    float4 fr = __ldg(f4p + lane);
    float4 dr = __ldg(w4p + lane);
    float  bn = __ldg(bias + n);

    float4 f4;
    f4.x = (fr.x > 20.0f) ? fr.x : log1pf(expf(fr.x));
    f4.y = (fr.y > 20.0f) ? fr.y : log1pf(expf(fr.y));
    f4.z = (fr.z > 20.0f) ? fr.z : log1pf(expf(fr.z));
    f4.w = (fr.w > 20.0f) ? fr.w : log1pf(expf(fr.w));

    float4 w4;
    w4.x = f4.x * (-fabsf(dr.x));
    w4.y = f4.y * (-fabsf(dr.y));
    w4.z = f4.z * (-fabsf(dr.z));
    w4.w = f4.w * (-fabsf(dr.w));

    const int b0 = bh * (B_ / BSPLIT);
    const int b1 = b0 + (B_ / BSPLIT);

    const float4* q4base = reinterpret_cast<const float4*>(q);
    float4*       d4base = reinterpret_cast<float4*>(delta);

    for (int b = b0; b < b1; b++) {
        float4 q4 = __ldg(q4base + (size_t)b * (D_ / 4) + lane);

        float dx = q4.x - c4.x;
        float dy = q4.y - c4.y;
        float dz = q4.z - c4.z;
        float dwv = q4.w - c4.w;
        dx *= dx; dy *= dy; dz *= dz; dwv *= dwv;

        float4 o;
        o.x = dx * f4.x; o.y = dy * f4.y; o.z = dz * f4.z; o.w = dwv * f4.w;

        float a = dx * w4.x;
        a = fmaf(dy,  w4.y, a);
        a = fmaf(dz,  w4.z, a);
        a = fmaf(dwv, w4.w, a);

        // streaming store — evict-first, don't pollute L2 (delta never re-read)
        __stcs(&d4base[((size_t)b * N_ + n) * (D_ / 4) + lane], o);

        a += __shfl_xor_sync(0xffffffffu, a, 16);
        a += __shfl_xor_sync(0xffffffffu, a, 8);
        a += __shfl_xor_sync(0xffffffffu, a, 4);
        a += __shfl_xor_sync(0xffffffffu, a, 2);
        a += __shfl_xor_sync(0xffffffffu, a, 1);

        if (lane == 0) {
            float s  = a + bn;
            float av = 1.0f / (1.0f + expf(-s));
            act[(size_t)b * N_ + n] = av;   // normal store: stays L2-resident for epilogue
        }
    }
}

// ---------------------------------------------------------------------------
// yhat partials: grid = 32 b-groups x NCHUNK n-chunks = 512 blocks.
// Each block: 8 b rows x (N_/NCHUNK) n's. Warp w owns 4 c-columns.
// ---------------------------------------------------------------------------
__global__ void __launch_bounds__(256) yhat_partial_kernel(const float* __restrict__ act,
                                                           const float* __restrict__ targets)
{
    int chunk = blockIdx.x & (NCHUNK - 1);
    int bg    = blockIdx.x >> 4;          // 0..31
    int b0    = bg * 8;
    int w     = threadIdx.x >> 5;
    int lane  = threadIdx.x & 31;
    int c0    = w * 4;

    const int nper = N_ / NCHUNK;         // 256
    const int nst  = chunk * nper;

    float acc[8][4];
    float srow[8];
    #pragma unroll
    for (int i = 0; i < 8; i++) {
        srow[i] = 0.0f;
        #pragma unroll
        for (int j = 0; j < 4; j++) acc[i][j] = 0.0f;
    }

    #pragma unroll
    for (int it = 0; it < nper / 32; it++) {
        int n = nst + it * 32 + lane;
        float4 t = __ldg(reinterpret_cast<const float4*>(targets + (size_t)n * C_ + c0));
        #pragma unroll
        for (int i = 0; i < 8; i++) {
            float a = __ldg(act + (size_t)(b0 + i) * N_ + n);
            srow[i] += a;
            acc[i][0] = fmaf(a, t.x, acc[i][0]);
            acc[i][1] = fmaf(a, t.y, acc[i][1]);
            acc[i][2] = fmaf(a, t.z, acc[i][2]);
            acc[i][3] = fmaf(a, t.w, acc[i][3]);
        }
    }

    #pragma unroll
    for (int i = 0; i < 8; i++) {
        #pragma unroll
        for (int j = 0; j < 4; j++) {
            float v = acc[i][j];
            v += __shfl_xor_sync(0xffffffffu, v, 16);
            v += __shfl_xor_sync(0xffffffffu, v, 8);
            v += __shfl_xor_sync(0xffffffffu, v, 4);
            v += __shfl_xor_sync(0xffffffffu, v, 2);
            v += __shfl_xor_sync(0xffffffffu, v, 1);
            acc[i][j] = v;
        }
        float s = srow[i];
        s += __shfl_xor_sync(0xffffffffu, s, 16);
        s += __shfl_xor_sync(0xffffffffu, s, 8);
        s += __shfl_xor_sync(0xffffffffu, s, 4);
        s += __shfl_xor_sync(0xffffffffu, s, 2);
        s += __shfl_xor_sync(0xffffffffu, s, 1);
        srow[i] = s;
    }

    if (lane == 0) {
        #pragma unroll
        for (int i = 0; i < 8; i++) {
            #pragma unroll
            for (int j = 0; j < 4; j++)
                g_partial[chunk][b0 + i][c0 + j] = acc[i][j];
            if (w == 0) g_psum[chunk][b0 + i] = srow[i];
        }
    }
}

// ---------------------------------------------------------------------------
// Final reduce: one thread per (b, c) output; 16-way partial sums (L2-hot).
// ---------------------------------------------------------------------------
__global__ void __launch_bounds__(256) yhat_reduce_kernel(float* __restrict__ yhat)
{
    int idx = blockIdx.x * blockDim.x + threadIdx.x;   // 0 .. B_*C_-1
    int b = idx >> 5;
    int c = idx & (C_ - 1);

    float v = 0.0f, s = 0.0f;
    #pragma unroll
    for (int k = 0; k < NCHUNK; k++) {
        v += g_partial[k][b][c];
        s += g_psum[k][b];
    }
    yhat[idx] = v / (s + 0.01f);
}

// ---------------------------------------------------------------------------
// Launch. Inputs: queries, cases, targets, feature_weights, distance_weights,
// ca_bias. Output layout: y_hat | activations | delta.
// ---------------------------------------------------------------------------
extern "C" void kernel_launch(void* const* d_in, const int* in_sizes, int n_in,
                              void* d_out, int out_size)
{
    const float* queries = (const float*)d_in[0];
    const float* cases   = (const float*)d_in[1];
    const float* targets = (const float*)d_in[2];
    const float* fw      = (const float*)d_in[3];
    const float* dw      = (const float*)d_in[4];
    const float* bias    = (const float*)d_in[5];

    float* out   = (float*)d_out;
    float* yhat  = out;                                   // B*C
    float* act   = out + (size_t)B_ * C_;                 // B*N
    float* delta = out + (size_t)B_ * C_ + (size_t)B_ * N_;

    int total_warps = N_ * BSPLIT;
    main_kernel<<<total_warps / 8, 256>>>(queries, cases, fw, dw, bias, delta, act);
    yhat_partial_kernel<<<32 * NCHUNK, 256>>>(act, targets);
    yhat_reduce_kernel<<<(B_ * C_) / 256, 256>>>(yhat);
}